// round 9
// baseline (speedup 1.0000x reference)
#include <cuda_runtime.h>
#include <cuda_bf16.h>
#include <cstdint>
#include <math.h>

#define NTOK   49
#define HEADS  6
#define DIM    192
#define DH     32
#define QSCALE 0.1767766952966369f

/* ================= device scratch (static: allocation-free) ================= */
__device__ float          g_qkv [200704u * 576u];
__device__ float          g_attn[200704u * 192u];
__device__ __nv_bfloat16  g_wqh[576 * 192], g_wql[576 * 192];
__device__ __nv_bfloat16  g_wph[192 * 192], g_wpl[192 * 192];
__device__ float          g_bias[HEADS * NTOK * NTOK];

__device__ __forceinline__ uint32_t pack_bf2(float a, float b) {
    __nv_bfloat16 ha = __float2bfloat16(a), hb = __float2bfloat16(b);
    return (uint32_t)__bfloat16_as_ushort(ha) | ((uint32_t)__bfloat16_as_ushort(hb) << 16);
}

/* ================= prep ================= */
__global__ void prep_kernel(const float* __restrict__ qkv_w, const float* __restrict__ proj_w,
                            const float* __restrict__ bias_table, const int* __restrict__ rel_idx)
{
    int i = blockIdx.x * 256 + threadIdx.x;
    if (i < 576 * 192) {
        float w = qkv_w[i];
        __nv_bfloat16 h = __float2bfloat16(w);
        g_wqh[i] = h;
        g_wql[i] = __float2bfloat16(w - __bfloat162float(h));
    }
    if (i < 192 * 192) {
        float w = proj_w[i];
        __nv_bfloat16 h = __float2bfloat16(w);
        g_wph[i] = h;
        g_wpl[i] = __float2bfloat16(w - __bfloat162float(h));
    }
    if (i < HEADS * NTOK * NTOK) {
        int m = i % NTOK, t = i / NTOK;
        int n = t % NTOK, h = t / NTOK;
        g_bias[i] = bias_table[rel_idx[n * NTOK + m] * HEADS + h];
    }
}

/* ================= mma / cp.async ================= */
__device__ __forceinline__ void mma16816(float* c, const uint32_t* a, const uint32_t* b) {
    asm volatile(
        "mma.sync.aligned.m16n8k16.row.col.f32.bf16.bf16.f32 "
        "{%0,%1,%2,%3}, {%4,%5,%6,%7}, {%8,%9}, {%0,%1,%2,%3};"
        : "+f"(c[0]), "+f"(c[1]), "+f"(c[2]), "+f"(c[3])
        : "r"(a[0]), "r"(a[1]), "r"(a[2]), "r"(a[3]), "r"(b[0]), "r"(b[1]));
}
__device__ __forceinline__ void cp16(uint32_t dst, const void* src) {
    asm volatile("cp.async.cg.shared.global [%0], [%1], 16;" :: "r"(dst), "l"(src));
}

/* ================ GEMM (exact R6 v2 — best measured) ================ */
#define APAD   200
#define A_H    0
#define A_L    (128 * APAD * 2)                /* 51200  */
#define B_BASE (2 * 128 * APAD * 2)            /* 102400 */
#define B_STEP 55296
#define B_LO   27648
#define GEMM_SMEM (B_BASE + 2 * B_STEP)        /* 212992 */

__global__ __launch_bounds__(256, 1)
void gemm_bf16x3(const float* __restrict__ A,
                 const __nv_bfloat16* __restrict__ Bhi,
                 const __nv_bfloat16* __restrict__ Blo,
                 const float* __restrict__ bias,
                 float* __restrict__ C, int ldc, int NT)
{
    extern __shared__ char smc[];
    uint32_t sb;
    asm("{ .reg .u64 t; cvta.to.shared.u64 t, %1; cvt.u32.u64 %0, t; }" : "=r"(sb) : "l"(smc));

    const int tid = threadIdx.x, wid = tid >> 5, lane = tid & 31;
    const int mtile = blockIdx.x;
    const int wm = (wid & 3) * 32;
    const int wn = (wid >> 2) * 96;
    const int L  = 3 * NT;

    auto prefetch = [&](int idx) {
        int nt = idx / 3, kc = idx - nt * 3;
        const __nv_bfloat16* bh = Bhi + (size_t)nt * 192 * 192 + kc * 64;
        const __nv_bfloat16* bl = Blo + (size_t)nt * 192 * 192 + kc * 64;
        uint32_t dst = sb + B_BASE + (idx & 1) * B_STEP;
        #pragma unroll
        for (int it = 0; it < 6; it++) {
            int g = tid + it * 256;
            int row = g >> 3, c8 = g & 7;
            cp16(dst + row * 144 + c8 * 16, bh + row * 192 + c8 * 8);
            cp16(dst + B_LO + row * 144 + c8 * 16, bl + row * 192 + c8 * 8);
        }
        asm volatile("cp.async.commit_group;" ::: "memory");
    };

    prefetch(0);
    if (L > 1) prefetch(1);

    {
        const float* Abase = A + (size_t)mtile * 128 * 192;
        #pragma unroll
        for (int it = 0; it < 24; it++) {
            int g = tid + it * 256;
            int row = g / 48, c4 = (g % 48) * 4;
            float4 f = *(const float4*)(Abase + row * 192 + c4);
            uint32_t h0 = pack_bf2(f.x, f.y), h1 = pack_bf2(f.z, f.w);
            float rx = f.x - __bfloat162float(__ushort_as_bfloat16((unsigned short)h0));
            float ry = f.y - __bfloat162float(__ushort_as_bfloat16((unsigned short)(h0 >> 16)));
            float rz = f.z - __bfloat162float(__ushort_as_bfloat16((unsigned short)h1));
            float rw = f.w - __bfloat162float(__ushort_as_bfloat16((unsigned short)(h1 >> 16)));
            *(uint2*)(smc + A_H + row * 400 + c4 * 2) = make_uint2(h0, h1);
            *(uint2*)(smc + A_L + row * 400 + c4 * 2) =
                make_uint2(pack_bf2(rx, ry), pack_bf2(rz, rw));
        }
    }
    __syncthreads();

    float acc[2][12][4];

    for (int nt = 0; nt < NT; nt++) {
        #pragma unroll
        for (int mf = 0; mf < 2; mf++)
            #pragma unroll
            for (int nf = 0; nf < 12; nf++)
                #pragma unroll
                for (int j = 0; j < 4; j++) acc[mf][nf][j] = 0.f;

        for (int kc = 0; kc < 3; kc++) {
            const int idx = nt * 3 + kc;
            if (idx < L - 1) asm volatile("cp.async.wait_group 1;" ::: "memory");
            else             asm volatile("cp.async.wait_group 0;" ::: "memory");
            __syncthreads();

            const char* bb = smc + B_BASE + (idx & 1) * B_STEP;

            #pragma unroll
            for (int ks = 0; ks < 4; ks++) {
                const int kk  = ks * 16 + (lane & 3) * 2;
                const int kxg = kc * 64 + kk;

                uint32_t ah[2][4], al[2][4];
                #pragma unroll
                for (int mf = 0; mf < 2; mf++)
                    #pragma unroll
                    for (int j = 0; j < 4; j++) {
                        int rr = wm + mf * 16 + (lane >> 2) + (j & 1) * 8;
                        int kx = kxg + (j >> 1) * 8;
                        ah[mf][j] = *(const uint32_t*)(smc + A_H + rr * 400 + kx * 2);
                        al[mf][j] = *(const uint32_t*)(smc + A_L + rr * 400 + kx * 2);
                    }

                uint32_t bh[12][2], bl[12][2];
                #pragma unroll
                for (int nf = 0; nf < 12; nf++) {
                    int n = wn + nf * 8 + (lane >> 2);
                    bh[nf][0] = *(const uint32_t*)(bb + n * 144 + kk * 2);
                    bh[nf][1] = *(const uint32_t*)(bb + n * 144 + (kk + 8) * 2);
                    bl[nf][0] = *(const uint32_t*)(bb + B_LO + n * 144 + kk * 2);
                    bl[nf][1] = *(const uint32_t*)(bb + B_LO + n * 144 + (kk + 8) * 2);
                }

                #pragma unroll
                for (int mf = 0; mf < 2; mf++)
                    #pragma unroll
                    for (int nf = 0; nf < 12; nf++) {
                        mma16816(acc[mf][nf], ah[mf], bh[nf]);
                        mma16816(acc[mf][nf], ah[mf], bl[nf]);
                        mma16816(acc[mf][nf], al[mf], bh[nf]);
                    }
            }
            __syncthreads();
            if (idx + 2 < L) prefetch(idx + 2);
        }

        #pragma unroll
        for (int mf = 0; mf < 2; mf++) {
            size_t r0 = (size_t)mtile * 128 + wm + mf * 16 + (lane >> 2);
            #pragma unroll
            for (int nf = 0; nf < 12; nf++) {
                int c = nt * 192 + wn + nf * 8 + (lane & 3) * 2;
                float b0 = __ldg(bias + c), b1 = __ldg(bias + c + 1);
                *(float2*)(C + r0 * ldc + c) =
                    make_float2(acc[mf][nf][0] + b0, acc[mf][nf][1] + b1);
                *(float2*)(C + (r0 + 8) * ldc + c) =
                    make_float2(acc[mf][nf][2] + b0, acc[mf][nf][3] + b1);
            }
        }
    }
}

/* ================= K2 v2: convert-once, barrier-free attention =================
   256 thr/window. One conversion pass builds:
     QK hi/lo: [64 rows][392 pad] bf16 (cols 0..191 = q*scale, 192..383 = k)
     VT hi/lo: [192 rows][72 pad] bf16 (row = global d, col = token)
   Then 24 units (6 heads x 4 row-blocks) over 8 warps, no barriers. */
#define QKS   392                      /* QK row stride (bf16) */
#define VTS   72                       /* VT row stride (bf16) */
#define OFF_QKL (64 * QKS)
#define OFF_VTH (2 * 64 * QKS)
#define OFF_VTL (2 * 64 * QKS + 192 * VTS)
#define ATTN_SMEM ((2 * 64 * QKS + 2 * 192 * VTS) * 2)   /* 155,904 B */

__global__ __launch_bounds__(256, 1)
void attn_win()
{
    extern __shared__ __nv_bfloat16 sm[];
    __nv_bfloat16* sQKh = sm;
    __nv_bfloat16* sQKl = sm + OFF_QKL;
    __nv_bfloat16* sVTh = sm + OFF_VTH;
    __nv_bfloat16* sVTl = sm + OFF_VTL;

    const int tid  = threadIdx.x;
    const int wid  = tid >> 5, lane = tid & 31;
    const int b    = blockIdx.x;
    const int l4   = lane >> 2, lm = lane & 3;

    /* zero pads that feed MMAs:
       QK rows 49..63 (K cols masked, Q rows unstored — but keep finite) */
    if (tid < 192) {
        #pragma unroll
        for (int c = 49; c < 64; c++) {
            sVTh[tid * VTS + c] = __nv_bfloat16(0.f);
            sVTl[tid * VTS + c] = __nv_bfloat16(0.f);
        }
    } else {
        int r = 49 + (tid - 192) % 15;           /* rows 49..63, covered by 64 thr */
        int half = (tid - 192) / 15;             /* not full coverage; finish below */
        (void)half;
    }
    /* zero QK pad rows 49..63 fully (both arrays), vector stores: 15*392*2 bf16 */
    for (int i = tid; i < 15 * QKS / 2; i += 256) {
        int r = 49 + i / (QKS / 2), c = (i % (QKS / 2)) * 2;
        *(uint32_t*)&sQKh[r * QKS + c] = 0u;
        *(uint32_t*)&sQKl[r * QKS + c] = 0u;
    }

    /* ---- conversion pass: 49 x 576 fp32 -> tiles (cols<49 only; no race with pads) */
    const float* qkvw = g_qkv + (size_t)b * (NTOK * 576);
    for (int it = 0; it < 28; it++) {
        int g = tid + it * 256;                  /* 7056 float4 groups */
        if (g < NTOK * 144) {
            int n = g / 144, c4 = (g - n * 144) * 4;
            float4 f = *(const float4*)(qkvw + n * 576 + c4);
            if (c4 < 384) {
                float s = (c4 < 192) ? QSCALE : 1.f;
                float vx = f.x * s, vy = f.y * s, vz = f.z * s, vw = f.w * s;
                uint32_t h0 = pack_bf2(vx, vy), h1 = pack_bf2(vz, vw);
                float rx = vx - __bfloat162float(__ushort_as_bfloat16((unsigned short)h0));
                float ry = vy - __bfloat162float(__ushort_as_bfloat16((unsigned short)(h0 >> 16)));
                float rz = vz - __bfloat162float(__ushort_as_bfloat16((unsigned short)h1));
                float rw = vw - __bfloat162float(__ushort_as_bfloat16((unsigned short)(h1 >> 16)));
                *(uint2*)&sQKh[n * QKS + c4] = make_uint2(h0, h1);
                *(uint2*)&sQKl[n * QKS + c4] = make_uint2(pack_bf2(rx, ry), pack_bf2(rz, rw));
            } else {
                int d = c4 - 384;
                float v[4] = {f.x, f.y, f.z, f.w};
                #pragma unroll
                for (int j = 0; j < 4; j++) {
                    __nv_bfloat16 h = __float2bfloat16(v[j]);
                    sVTh[(d + j) * VTS + n] = h;
                    sVTl[(d + j) * VTS + n] = __float2bfloat16(v[j] - __bfloat162float(h));
                }
            }
        }
    }
    __syncthreads();

    /* ---- 24 units: h = u>>2, row-block = u&3; no barriers ---- */
    for (int u = wid; u < 24; u += 8) {
        const int h   = u >> 2;
        const int blk = u & 3;
        const int r0  = blk * 16 + l4;
        const int qcol = h * DH;                 /* q cols in QK tile */
        const int kcol = 192 + h * DH;           /* k cols */

        uint32_t qh[2][4], ql[2][4];
        #pragma unroll
        for (int kf = 0; kf < 2; kf++)
            #pragma unroll
            for (int j = 0; j < 4; j++) {
                int rr = r0 + (j & 1) * 8;
                int kx = qcol + kf * 16 + lm * 2 + (j >> 1) * 8;
                qh[kf][j] = *(const uint32_t*)&sQKh[rr * QKS + kx];
                ql[kf][j] = *(const uint32_t*)&sQKl[rr * QKS + kx];
            }

        float acc[7][4];
        #pragma unroll
        for (int nf = 0; nf < 7; nf++)
            #pragma unroll
            for (int j = 0; j < 4; j++) acc[nf][j] = 0.f;

        #pragma unroll
        for (int nf = 0; nf < 7; nf++) {
            int n = nf * 8 + l4;
            #pragma unroll
            for (int kf = 0; kf < 2; kf++) {
                int kx = kcol + kf * 16 + lm * 2;
                uint32_t bh[2], bl[2];
                bh[0] = *(const uint32_t*)&sQKh[n * QKS + kx];
                bh[1] = *(const uint32_t*)&sQKh[n * QKS + kx + 8];
                bl[0] = *(const uint32_t*)&sQKl[n * QKS + kx];
                bl[1] = *(const uint32_t*)&sQKl[n * QKS + kx + 8];
                mma16816(acc[nf], qh[kf], bh);
                mma16816(acc[nf], ql[kf], bh);
                mma16816(acc[nf], qh[kf], bl);
            }
        }

        const int ra = r0, rb = r0 + 8;
        const float* biasA = g_bias + (h * NTOK + ra) * NTOK;
        const float* biasB = g_bias + (h * NTOK + rb) * NTOK;
        float ma = -1e30f, mb = -1e30f;
        #pragma unroll
        for (int nf = 0; nf < 7; nf++) {
            int c0 = nf * 8 + lm * 2, c1 = c0 + 1;
            float ba0 = (ra < NTOK && c0 < NTOK) ? __ldg(biasA + c0) : 0.f;
            float ba1 = (ra < NTOK && c1 < NTOK) ? __ldg(biasA + c1) : 0.f;
            float bb0 = (rb < NTOK && c0 < NTOK) ? __ldg(biasB + c0) : 0.f;
            float bb1 = (rb < NTOK && c1 < NTOK) ? __ldg(biasB + c1) : 0.f;
            acc[nf][0] = (c0 < NTOK) ? acc[nf][0] + ba0 : -1e30f;
            acc[nf][1] = (c1 < NTOK) ? acc[nf][1] + ba1 : -1e30f;
            acc[nf][2] = (c0 < NTOK) ? acc[nf][2] + bb0 : -1e30f;
            acc[nf][3] = (c1 < NTOK) ? acc[nf][3] + bb1 : -1e30f;
            ma = fmaxf(ma, fmaxf(acc[nf][0], acc[nf][1]));
            mb = fmaxf(mb, fmaxf(acc[nf][2], acc[nf][3]));
        }
        ma = fmaxf(ma, __shfl_xor_sync(0xffffffffu, ma, 1));
        ma = fmaxf(ma, __shfl_xor_sync(0xffffffffu, ma, 2));
        mb = fmaxf(mb, __shfl_xor_sync(0xffffffffu, mb, 1));
        mb = fmaxf(mb, __shfl_xor_sync(0xffffffffu, mb, 2));

        float sa = 0.f, sb2 = 0.f;
        #pragma unroll
        for (int nf = 0; nf < 7; nf++) {
            acc[nf][0] = __expf(acc[nf][0] - ma);
            acc[nf][1] = __expf(acc[nf][1] - ma);
            acc[nf][2] = __expf(acc[nf][2] - mb);
            acc[nf][3] = __expf(acc[nf][3] - mb);
            sa  += acc[nf][0] + acc[nf][1];
            sb2 += acc[nf][2] + acc[nf][3];
        }
        sa  += __shfl_xor_sync(0xffffffffu, sa, 1);
        sa  += __shfl_xor_sync(0xffffffffu, sa, 2);
        sb2 += __shfl_xor_sync(0xffffffffu, sb2, 1);
        sb2 += __shfl_xor_sync(0xffffffffu, sb2, 2);
        float inva = 1.f / sa, invb = 1.f / sb2;
        #pragma unroll
        for (int nf = 0; nf < 7; nf++) {
            acc[nf][0] *= inva; acc[nf][1] *= inva;
            acc[nf][2] *= invb; acc[nf][3] *= invb;
        }

        uint32_t pah[4][4], pal[4][4];
        #pragma unroll
        for (int kf = 0; kf < 4; kf++) {
            #pragma unroll
            for (int half = 0; half < 2; half++) {
                int nf = 2 * kf + half;
                if (nf < 7) {
                    float p0 = acc[nf][0], p1 = acc[nf][1];
                    float p2 = acc[nf][2], p3 = acc[nf][3];
                    uint32_t h01 = pack_bf2(p0, p1), h23 = pack_bf2(p2, p3);
                    float r0f = p0 - __bfloat162float(__ushort_as_bfloat16((unsigned short)h01));
                    float r1f = p1 - __bfloat162float(__ushort_as_bfloat16((unsigned short)(h01 >> 16)));
                    float r2f = p2 - __bfloat162float(__ushort_as_bfloat16((unsigned short)h23));
                    float r3f = p3 - __bfloat162float(__ushort_as_bfloat16((unsigned short)(h23 >> 16)));
                    pah[kf][half * 2]     = h01;
                    pah[kf][half * 2 + 1] = h23;
                    pal[kf][half * 2]     = pack_bf2(r0f, r1f);
                    pal[kf][half * 2 + 1] = pack_bf2(r2f, r3f);
                } else {
                    pah[kf][half * 2] = 0u; pah[kf][half * 2 + 1] = 0u;
                    pal[kf][half * 2] = 0u; pal[kf][half * 2 + 1] = 0u;
                }
            }
        }

        float oacc[4][4];
        #pragma unroll
        for (int nf = 0; nf < 4; nf++)
            #pragma unroll
            for (int j = 0; j < 4; j++) oacc[nf][j] = 0.f;

        #pragma unroll
        for (int nf = 0; nf < 4; nf++) {
            int dh = h * DH + nf * 8 + l4;       /* global d row in VT */
            #pragma unroll
            for (int kf = 0; kf < 4; kf++) {
                int kx = kf * 16 + lm * 2;
                uint32_t bh[2], bl[2];
                bh[0] = *(const uint32_t*)&sVTh[dh * VTS + kx];
                bh[1] = *(const uint32_t*)&sVTh[dh * VTS + kx + 8];
                bl[0] = *(const uint32_t*)&sVTl[dh * VTS + kx];
                bl[1] = *(const uint32_t*)&sVTl[dh * VTS + kx + 8];
                mma16816(oacc[nf], pah[kf], bh);
                mma16816(oacc[nf], pal[kf], bh);
                mma16816(oacc[nf], pah[kf], bl);
            }
        }

        if (ra < NTOK) {
            float* orow = g_attn + ((size_t)b * NTOK + ra) * DIM + h * DH;
            #pragma unroll
            for (int nf = 0; nf < 4; nf++)
                *(float2*)(orow + nf * 8 + lm * 2) = make_float2(oacc[nf][0], oacc[nf][1]);
        }
        if (rb < NTOK) {
            float* orow = g_attn + ((size_t)b * NTOK + rb) * DIM + h * DH;
            #pragma unroll
            for (int nf = 0; nf < 4; nf++)
                *(float2*)(orow + nf * 8 + lm * 2) = make_float2(oacc[nf][2], oacc[nf][3]);
        }
    }
}

/* ================= host ================= */
extern "C" void kernel_launch(void* const* d_in, const int* in_sizes, int n_in,
                              void* d_out, int out_size)
{
    const float* x          = (const float*)d_in[0];
    const float* qkv_w      = (const float*)d_in[1];
    const float* qkv_b      = (const float*)d_in[2];
    const float* proj_w     = (const float*)d_in[3];
    const float* proj_b     = (const float*)d_in[4];
    const float* bias_table = (const float*)d_in[5];
    const int*   rel_idx    = (const int*)d_in[6];
    float*       out        = (float*)d_out;

    const int nB = in_sizes[0] / (NTOK * DIM);       /* 4096 */
    const int mt = (nB * NTOK) / 128;                /* 1568 */

    void *p_qkv, *p_attn, *p_wqh, *p_wql, *p_wph, *p_wpl;
    cudaGetSymbolAddress(&p_qkv,  g_qkv);
    cudaGetSymbolAddress(&p_attn, g_attn);
    cudaGetSymbolAddress(&p_wqh,  g_wqh);
    cudaGetSymbolAddress(&p_wql,  g_wql);
    cudaGetSymbolAddress(&p_wph,  g_wph);
    cudaGetSymbolAddress(&p_wpl,  g_wpl);

    cudaFuncSetAttribute(gemm_bf16x3, cudaFuncAttributeMaxDynamicSharedMemorySize, GEMM_SMEM);
    cudaFuncSetAttribute(attn_win,    cudaFuncAttributeMaxDynamicSharedMemorySize, ATTN_SMEM);

    prep_kernel<<<432, 256>>>(qkv_w, proj_w, bias_table, rel_idx);

    gemm_bf16x3<<<mt, 256, GEMM_SMEM>>>(
        x, (const __nv_bfloat16*)p_wqh, (const __nv_bfloat16*)p_wql,
        qkv_b, (float*)p_qkv, 576, 3);

    attn_win<<<nB, 256, ATTN_SMEM>>>();

    gemm_bf16x3<<<mt, 256, GEMM_SMEM>>>(
        (const float*)p_attn, (const __nv_bfloat16*)p_wph, (const __nv_bfloat16*)p_wpl,
        proj_b, out, 192, 1);
}

// round 11
// speedup vs baseline: 1.3548x; 1.3548x over previous
#include <cuda_runtime.h>
#include <cuda_bf16.h>
#include <cstdint>
#include <math.h>

#define NTOK   49
#define HEADS  6
#define DIM    192
#define DH     32
#define QSCALE 0.1767766952966369f

/* ================= device scratch (static: allocation-free) ================= */
__device__ float          g_qkv [200704u * 576u];
__device__ float          g_attn[200704u * 192u];
__device__ __nv_bfloat16  g_wqh[576 * 192], g_wql[576 * 192];
__device__ __nv_bfloat16  g_wph[192 * 192], g_wpl[192 * 192];
__device__ float          g_bias[HEADS * NTOK * NTOK];

__device__ __forceinline__ uint32_t pack_bf2(float a, float b) {
    __nv_bfloat16 ha = __float2bfloat16(a), hb = __float2bfloat16(b);
    return (uint32_t)__bfloat16_as_ushort(ha) | ((uint32_t)__bfloat16_as_ushort(hb) << 16);
}

/* ================= prep ================= */
__global__ void prep_kernel(const float* __restrict__ qkv_w, const float* __restrict__ proj_w,
                            const float* __restrict__ bias_table, const int* __restrict__ rel_idx)
{
    int i = blockIdx.x * 256 + threadIdx.x;
    if (i < 576 * 192) {
        float w = qkv_w[i];
        __nv_bfloat16 h = __float2bfloat16(w);
        g_wqh[i] = h;
        g_wql[i] = __float2bfloat16(w - __bfloat162float(h));
    }
    if (i < 192 * 192) {
        float w = proj_w[i];
        __nv_bfloat16 h = __float2bfloat16(w);
        g_wph[i] = h;
        g_wpl[i] = __float2bfloat16(w - __bfloat162float(h));
    }
    if (i < HEADS * NTOK * NTOK) {
        int m = i % NTOK, t = i / NTOK;
        int n = t % NTOK, h = t / NTOK;
        g_bias[i] = bias_table[rel_idx[n * NTOK + m] * HEADS + h];
    }
}

/* ================= mma / cp.async ================= */
__device__ __forceinline__ void mma16816(float* c, const uint32_t* a, const uint32_t* b) {
    asm volatile(
        "mma.sync.aligned.m16n8k16.row.col.f32.bf16.bf16.f32 "
        "{%0,%1,%2,%3}, {%4,%5,%6,%7}, {%8,%9}, {%0,%1,%2,%3};"
        : "+f"(c[0]), "+f"(c[1]), "+f"(c[2]), "+f"(c[3])
        : "r"(a[0]), "r"(a[1]), "r"(a[2]), "r"(a[3]), "r"(b[0]), "r"(b[1]));
}
__device__ __forceinline__ void cp16(uint32_t dst, const void* src) {
    asm volatile("cp.async.cg.shared.global [%0], [%1], 16;" :: "r"(dst), "l"(src));
}

/* ================ GEMM (exact R6 v2 — best measured; DO NOT TOUCH) ================ */
#define APAD   200
#define A_H    0
#define A_L    (128 * APAD * 2)                /* 51200  */
#define B_BASE (2 * 128 * APAD * 2)            /* 102400 */
#define B_STEP 55296
#define B_LO   27648
#define GEMM_SMEM (B_BASE + 2 * B_STEP)        /* 212992 */

__global__ __launch_bounds__(256, 1)
void gemm_bf16x3(const float* __restrict__ A,
                 const __nv_bfloat16* __restrict__ Bhi,
                 const __nv_bfloat16* __restrict__ Blo,
                 const float* __restrict__ bias,
                 float* __restrict__ C, int ldc, int NT)
{
    extern __shared__ char smc[];
    uint32_t sb;
    asm("{ .reg .u64 t; cvta.to.shared.u64 t, %1; cvt.u32.u64 %0, t; }" : "=r"(sb) : "l"(smc));

    const int tid = threadIdx.x, wid = tid >> 5, lane = tid & 31;
    const int mtile = blockIdx.x;
    const int wm = (wid & 3) * 32;
    const int wn = (wid >> 2) * 96;
    const int L  = 3 * NT;

    auto prefetch = [&](int idx) {
        int nt = idx / 3, kc = idx - nt * 3;
        const __nv_bfloat16* bh = Bhi + (size_t)nt * 192 * 192 + kc * 64;
        const __nv_bfloat16* bl = Blo + (size_t)nt * 192 * 192 + kc * 64;
        uint32_t dst = sb + B_BASE + (idx & 1) * B_STEP;
        #pragma unroll
        for (int it = 0; it < 6; it++) {
            int g = tid + it * 256;
            int row = g >> 3, c8 = g & 7;
            cp16(dst + row * 144 + c8 * 16, bh + row * 192 + c8 * 8);
            cp16(dst + B_LO + row * 144 + c8 * 16, bl + row * 192 + c8 * 8);
        }
        asm volatile("cp.async.commit_group;" ::: "memory");
    };

    prefetch(0);
    if (L > 1) prefetch(1);

    {
        const float* Abase = A + (size_t)mtile * 128 * 192;
        #pragma unroll
        for (int it = 0; it < 24; it++) {
            int g = tid + it * 256;
            int row = g / 48, c4 = (g % 48) * 4;
            float4 f = *(const float4*)(Abase + row * 192 + c4);
            uint32_t h0 = pack_bf2(f.x, f.y), h1 = pack_bf2(f.z, f.w);
            float rx = f.x - __bfloat162float(__ushort_as_bfloat16((unsigned short)h0));
            float ry = f.y - __bfloat162float(__ushort_as_bfloat16((unsigned short)(h0 >> 16)));
            float rz = f.z - __bfloat162float(__ushort_as_bfloat16((unsigned short)h1));
            float rw = f.w - __bfloat162float(__ushort_as_bfloat16((unsigned short)(h1 >> 16)));
            *(uint2*)(smc + A_H + row * 400 + c4 * 2) = make_uint2(h0, h1);
            *(uint2*)(smc + A_L + row * 400 + c4 * 2) =
                make_uint2(pack_bf2(rx, ry), pack_bf2(rz, rw));
        }
    }
    __syncthreads();

    float acc[2][12][4];

    for (int nt = 0; nt < NT; nt++) {
        #pragma unroll
        for (int mf = 0; mf < 2; mf++)
            #pragma unroll
            for (int nf = 0; nf < 12; nf++)
                #pragma unroll
                for (int j = 0; j < 4; j++) acc[mf][nf][j] = 0.f;

        for (int kc = 0; kc < 3; kc++) {
            const int idx = nt * 3 + kc;
            if (idx < L - 1) asm volatile("cp.async.wait_group 1;" ::: "memory");
            else             asm volatile("cp.async.wait_group 0;" ::: "memory");
            __syncthreads();

            const char* bb = smc + B_BASE + (idx & 1) * B_STEP;

            #pragma unroll
            for (int ks = 0; ks < 4; ks++) {
                const int kk  = ks * 16 + (lane & 3) * 2;
                const int kxg = kc * 64 + kk;

                uint32_t ah[2][4], al[2][4];
                #pragma unroll
                for (int mf = 0; mf < 2; mf++)
                    #pragma unroll
                    for (int j = 0; j < 4; j++) {
                        int rr = wm + mf * 16 + (lane >> 2) + (j & 1) * 8;
                        int kx = kxg + (j >> 1) * 8;
                        ah[mf][j] = *(const uint32_t*)(smc + A_H + rr * 400 + kx * 2);
                        al[mf][j] = *(const uint32_t*)(smc + A_L + rr * 400 + kx * 2);
                    }

                uint32_t bh[12][2], bl[12][2];
                #pragma unroll
                for (int nf = 0; nf < 12; nf++) {
                    int n = wn + nf * 8 + (lane >> 2);
                    bh[nf][0] = *(const uint32_t*)(bb + n * 144 + kk * 2);
                    bh[nf][1] = *(const uint32_t*)(bb + n * 144 + (kk + 8) * 2);
                    bl[nf][0] = *(const uint32_t*)(bb + B_LO + n * 144 + kk * 2);
                    bl[nf][1] = *(const uint32_t*)(bb + B_LO + n * 144 + (kk + 8) * 2);
                }

                #pragma unroll
                for (int mf = 0; mf < 2; mf++)
                    #pragma unroll
                    for (int nf = 0; nf < 12; nf++) {
                        mma16816(acc[mf][nf], ah[mf], bh[nf]);
                        mma16816(acc[mf][nf], ah[mf], bl[nf]);
                        mma16816(acc[mf][nf], al[mf], bh[nf]);
                    }
            }
            __syncthreads();
            if (idx + 2 < L) prefetch(idx + 2);
        }

        #pragma unroll
        for (int mf = 0; mf < 2; mf++) {
            size_t r0 = (size_t)mtile * 128 + wm + mf * 16 + (lane >> 2);
            #pragma unroll
            for (int nf = 0; nf < 12; nf++) {
                int c = nt * 192 + wn + nf * 8 + (lane & 3) * 2;
                float b0 = __ldg(bias + c), b1 = __ldg(bias + c + 1);
                *(float2*)(C + r0 * ldc + c) =
                    make_float2(acc[mf][nf][0] + b0, acc[mf][nf][1] + b1);
                *(float2*)(C + (r0 + 8) * ldc + c) =
                    make_float2(acc[mf][nf][2] + b0, acc[mf][nf][3] + b1);
            }
        }
    }
}

/* ================= K2 v4: head-pair attention, 256 threads (8 warps) ===========
   3 iterations of 2 heads: warps 0-3 -> head 2hp (rows 0..63 via 16-row blocks),
   warps 4-7 -> head 2hp+1. Unit body identical to the proven R5 kernel. */
#define TQ 2304              /* 64 x 36 */
#define TK 2016              /* 56 x 36 */
#define TV 2112              /* 32 x 66 */
#define O_QH 0
#define O_QL (2 * TQ)
#define O_KH (4 * TQ)
#define O_KL (4 * TQ + 2 * TK)
#define O_VH (4 * TQ + 4 * TK)
#define O_VL (4 * TQ + 4 * TK + 2 * TV)
#define ATTN_ELEMS (4 * TQ + 4 * TK + 4 * TV)   /* 25728 bf16 */
#define ATTN_SMEM  (ATTN_ELEMS * 2)             /* 51456 B */

__global__ __launch_bounds__(256, 2)
void attn_win()
{
    extern __shared__ __nv_bfloat16 sm[];

    const int tid  = threadIdx.x;
    const int wid  = tid >> 5, lane = tid & 31;
    const int b    = blockIdx.x;
    const int l4   = lane >> 2, lm = lane & 3;

    /* zero everything once; per-pair writes never touch pads */
    for (int i = tid; i < ATTN_ELEMS / 2; i += 256)
        *(uint32_t*)&sm[i * 2] = 0u;

    const float* qkvw = g_qkv + (size_t)b * (NTOK * 576);

    const int su  = wid >> 2;                 /* 0: even head, 1: odd head */
    const int r0  = (wid & 3) * 16 + l4;      /* rows 0..63 */

    for (int hp = 0; hp < 3; hp++) {
        __syncthreads();   /* previous pair's reads done before overwrite */

        /* ---- convert 2 heads: 49 rows x 64 cols (2x32) ---- */
        for (int idx = tid; idx < NTOK * 64; idx += 256) {
            int r = idx >> 6, c = idx & 63;
            int s = c >> 5, d = c & 31;
            const float* rowp = qkvw + r * 576 + (hp * 2 + s) * 32 + d;
            float qv = rowp[0] * QSCALE;
            float kv = rowp[192];
            float vv = rowp[384];
            __nv_bfloat16 qh = __float2bfloat16(qv);
            __nv_bfloat16 kh = __float2bfloat16(kv);
            __nv_bfloat16 vh = __float2bfloat16(vv);
            sm[O_QH + s * TQ + r * 36 + d] = qh;
            sm[O_QL + s * TQ + r * 36 + d] = __float2bfloat16(qv - __bfloat162float(qh));
            sm[O_KH + s * TK + r * 36 + d] = kh;
            sm[O_KL + s * TK + r * 36 + d] = __float2bfloat16(kv - __bfloat162float(kh));
            sm[O_VH + s * TV + d * 66 + r] = vh;
            sm[O_VL + s * TV + d * 66 + r] = __float2bfloat16(vv - __bfloat162float(vh));
        }
        __syncthreads();

        const int h = hp * 2 + su;
        const __nv_bfloat16* tQh = sm + O_QH + su * TQ;
        const __nv_bfloat16* tQl = sm + O_QL + su * TQ;
        const __nv_bfloat16* tKh = sm + O_KH + su * TK;
        const __nv_bfloat16* tKl = sm + O_KL + su * TK;
        const __nv_bfloat16* tVh = sm + O_VH + su * TV;
        const __nv_bfloat16* tVl = sm + O_VL + su * TV;

        /* ---- Q a-frags ---- */
        uint32_t qh[2][4], ql[2][4];
        #pragma unroll
        for (int kf = 0; kf < 2; kf++)
            #pragma unroll
            for (int j = 0; j < 4; j++) {
                int rr = r0 + (j & 1) * 8;
                int kx = kf * 16 + lm * 2 + (j >> 1) * 8;
                qh[kf][j] = *(const uint32_t*)&tQh[rr * 36 + kx];
                ql[kf][j] = *(const uint32_t*)&tQl[rr * 36 + kx];
            }

        /* ---- S = Q K^T ---- */
        float acc[7][4];
        #pragma unroll
        for (int nf = 0; nf < 7; nf++)
            #pragma unroll
            for (int j = 0; j < 4; j++) acc[nf][j] = 0.f;

        #pragma unroll
        for (int nf = 0; nf < 7; nf++) {
            int n = nf * 8 + l4;
            #pragma unroll
            for (int kf = 0; kf < 2; kf++) {
                uint32_t bh[2], bl[2];
                bh[0] = *(const uint32_t*)&tKh[n * 36 + kf * 16 + lm * 2];
                bh[1] = *(const uint32_t*)&tKh[n * 36 + kf * 16 + lm * 2 + 8];
                bl[0] = *(const uint32_t*)&tKl[n * 36 + kf * 16 + lm * 2];
                bl[1] = *(const uint32_t*)&tKl[n * 36 + kf * 16 + lm * 2 + 8];
                mma16816(acc[nf], qh[kf], bh);
                mma16816(acc[nf], ql[kf], bh);
                mma16816(acc[nf], qh[kf], bl);
            }
        }

        /* ---- softmax ---- */
        const int ra = r0, rb = r0 + 8;
        const float* biasA = g_bias + (h * NTOK + ra) * NTOK;
        const float* biasB = g_bias + (h * NTOK + rb) * NTOK;
        float ma = -1e30f, mb = -1e30f;
        #pragma unroll
        for (int nf = 0; nf < 7; nf++) {
            int c0 = nf * 8 + lm * 2, c1 = c0 + 1;
            float ba0 = (ra < NTOK && c0 < NTOK) ? __ldg(biasA + c0) : 0.f;
            float ba1 = (ra < NTOK && c1 < NTOK) ? __ldg(biasA + c1) : 0.f;
            float bb0 = (rb < NTOK && c0 < NTOK) ? __ldg(biasB + c0) : 0.f;
            float bb1 = (rb < NTOK && c1 < NTOK) ? __ldg(biasB + c1) : 0.f;
            acc[nf][0] = (c0 < NTOK) ? acc[nf][0] + ba0 : -1e30f;
            acc[nf][1] = (c1 < NTOK) ? acc[nf][1] + ba1 : -1e30f;
            acc[nf][2] = (c0 < NTOK) ? acc[nf][2] + bb0 : -1e30f;
            acc[nf][3] = (c1 < NTOK) ? acc[nf][3] + bb1 : -1e30f;
            ma = fmaxf(ma, fmaxf(acc[nf][0], acc[nf][1]));
            mb = fmaxf(mb, fmaxf(acc[nf][2], acc[nf][3]));
        }
        ma = fmaxf(ma, __shfl_xor_sync(0xffffffffu, ma, 1));
        ma = fmaxf(ma, __shfl_xor_sync(0xffffffffu, ma, 2));
        mb = fmaxf(mb, __shfl_xor_sync(0xffffffffu, mb, 1));
        mb = fmaxf(mb, __shfl_xor_sync(0xffffffffu, mb, 2));

        float sa = 0.f, sb2 = 0.f;
        #pragma unroll
        for (int nf = 0; nf < 7; nf++) {
            acc[nf][0] = __expf(acc[nf][0] - ma);
            acc[nf][1] = __expf(acc[nf][1] - ma);
            acc[nf][2] = __expf(acc[nf][2] - mb);
            acc[nf][3] = __expf(acc[nf][3] - mb);
            sa  += acc[nf][0] + acc[nf][1];
            sb2 += acc[nf][2] + acc[nf][3];
        }
        sa  += __shfl_xor_sync(0xffffffffu, sa, 1);
        sa  += __shfl_xor_sync(0xffffffffu, sa, 2);
        sb2 += __shfl_xor_sync(0xffffffffu, sb2, 1);
        sb2 += __shfl_xor_sync(0xffffffffu, sb2, 2);
        float inva = 1.f / sa, invb = 1.f / sb2;
        #pragma unroll
        for (int nf = 0; nf < 7; nf++) {
            acc[nf][0] *= inva; acc[nf][1] *= inva;
            acc[nf][2] *= invb; acc[nf][3] *= invb;
        }

        /* ---- P hi/lo a-frags ---- */
        uint32_t pah[4][4], pal[4][4];
        #pragma unroll
        for (int kf = 0; kf < 4; kf++) {
            #pragma unroll
            for (int half = 0; half < 2; half++) {
                int nf = 2 * kf + half;
                if (nf < 7) {
                    float p0 = acc[nf][0], p1 = acc[nf][1];
                    float p2 = acc[nf][2], p3 = acc[nf][3];
                    uint32_t h01 = pack_bf2(p0, p1), h23 = pack_bf2(p2, p3);
                    float r0f = p0 - __bfloat162float(__ushort_as_bfloat16((unsigned short)h01));
                    float r1f = p1 - __bfloat162float(__ushort_as_bfloat16((unsigned short)(h01 >> 16)));
                    float r2f = p2 - __bfloat162float(__ushort_as_bfloat16((unsigned short)h23));
                    float r3f = p3 - __bfloat162float(__ushort_as_bfloat16((unsigned short)(h23 >> 16)));
                    pah[kf][half * 2]     = h01;
                    pah[kf][half * 2 + 1] = h23;
                    pal[kf][half * 2]     = pack_bf2(r0f, r1f);
                    pal[kf][half * 2 + 1] = pack_bf2(r2f, r3f);
                } else {
                    pah[kf][half * 2] = 0u; pah[kf][half * 2 + 1] = 0u;
                    pal[kf][half * 2] = 0u; pal[kf][half * 2 + 1] = 0u;
                }
            }
        }

        /* ---- O = P V ---- */
        float oacc[4][4];
        #pragma unroll
        for (int nf = 0; nf < 4; nf++)
            #pragma unroll
            for (int j = 0; j < 4; j++) oacc[nf][j] = 0.f;

        #pragma unroll
        for (int nf = 0; nf < 4; nf++) {
            int dh = nf * 8 + l4;
            #pragma unroll
            for (int kf = 0; kf < 4; kf++) {
                uint32_t bh[2], bl[2];
                bh[0] = *(const uint32_t*)&tVh[dh * 66 + kf * 16 + lm * 2];
                bh[1] = *(const uint32_t*)&tVh[dh * 66 + kf * 16 + lm * 2 + 8];
                bl[0] = *(const uint32_t*)&tVl[dh * 66 + kf * 16 + lm * 2];
                bl[1] = *(const uint32_t*)&tVl[dh * 66 + kf * 16 + lm * 2 + 8];
                mma16816(oacc[nf], pah[kf], bh);
                mma16816(oacc[nf], pal[kf], bh);
                mma16816(oacc[nf], pah[kf], bl);
            }
        }

        if (ra < NTOK) {
            float* orow = g_attn + ((size_t)b * NTOK + ra) * DIM + h * DH;
            #pragma unroll
            for (int nf = 0; nf < 4; nf++)
                *(float2*)(orow + nf * 8 + lm * 2) = make_float2(oacc[nf][0], oacc[nf][1]);
        }
        if (rb < NTOK) {
            float* orow = g_attn + ((size_t)b * NTOK + rb) * DIM + h * DH;
            #pragma unroll
            for (int nf = 0; nf < 4; nf++)
                *(float2*)(orow + nf * 8 + lm * 2) = make_float2(oacc[nf][2], oacc[nf][3]);
        }
    }
}

/* ================= host ================= */
extern "C" void kernel_launch(void* const* d_in, const int* in_sizes, int n_in,
                              void* d_out, int out_size)
{
    const float* x          = (const float*)d_in[0];
    const float* qkv_w      = (const float*)d_in[1];
    const float* qkv_b      = (const float*)d_in[2];
    const float* proj_w     = (const float*)d_in[3];
    const float* proj_b     = (const float*)d_in[4];
    const float* bias_table = (const float*)d_in[5];
    const int*   rel_idx    = (const int*)d_in[6];
    float*       out        = (float*)d_out;

    const int nB = in_sizes[0] / (NTOK * DIM);       /* 4096 */
    const int mt = (nB * NTOK) / 128;                /* 1568 */

    void *p_qkv, *p_attn, *p_wqh, *p_wql, *p_wph, *p_wpl;
    cudaGetSymbolAddress(&p_qkv,  g_qkv);
    cudaGetSymbolAddress(&p_attn, g_attn);
    cudaGetSymbolAddress(&p_wqh,  g_wqh);
    cudaGetSymbolAddress(&p_wql,  g_wql);
    cudaGetSymbolAddress(&p_wph,  g_wph);
    cudaGetSymbolAddress(&p_wpl,  g_wpl);

    cudaFuncSetAttribute(gemm_bf16x3, cudaFuncAttributeMaxDynamicSharedMemorySize, GEMM_SMEM);
    cudaFuncSetAttribute(attn_win,    cudaFuncAttributeMaxDynamicSharedMemorySize, ATTN_SMEM);

    prep_kernel<<<432, 256>>>(qkv_w, proj_w, bias_table, rel_idx);

    gemm_bf16x3<<<mt, 256, GEMM_SMEM>>>(
        x, (const __nv_bfloat16*)p_wqh, (const __nv_bfloat16*)p_wql,
        qkv_b, (float*)p_qkv, 576, 3);

    attn_win<<<nB, 256, ATTN_SMEM>>>();

    gemm_bf16x3<<<mt, 256, GEMM_SMEM>>>(
        (const float*)p_attn, (const __nv_bfloat16*)p_wph, (const __nv_bfloat16*)p_wpl,
        proj_b, out, 192, 1);
}

// round 12
// speedup vs baseline: 1.7840x; 1.3168x over previous
#include <cuda_runtime.h>
#include <cuda_fp16.h>
#include <cstdint>
#include <math.h>

#define NTOK   49
#define HEADS  6
#define DIM    192
#define DH     32
#define QSCALE 0.1767766952966369f

/* ================= device scratch (static: allocation-free) ================= */
__device__ float   g_qkv [200704u * 576u];
__device__ float   g_attn[200704u * 192u];
__device__ __half  g_wq[576 * 192];
__device__ __half  g_wp[192 * 192];
__device__ float   g_bias[HEADS * NTOK * NTOK];

__device__ __forceinline__ uint32_t hpack(__half a, __half b) {
    return (uint32_t)__half_as_ushort(a) | ((uint32_t)__half_as_ushort(b) << 16);
}

/* ================= prep: weights -> fp16 (RN), materialize bias ================= */
__global__ void prep_kernel(const float* __restrict__ qkv_w, const float* __restrict__ proj_w,
                            const float* __restrict__ bias_table, const int* __restrict__ rel_idx)
{
    int i = blockIdx.x * 256 + threadIdx.x;
    if (i < 576 * 192) g_wq[i] = __float2half_rn(qkv_w[i]);
    if (i < 192 * 192) g_wp[i] = __float2half_rn(proj_w[i]);
    if (i < HEADS * NTOK * NTOK) {
        int m = i % NTOK, t = i / NTOK;
        int n = t % NTOK, h = t / NTOK;
        g_bias[i] = bias_table[rel_idx[n * NTOK + m] * HEADS + h];
    }
}

/* ================= mma fp16 / cp.async ================= */
__device__ __forceinline__ void mma16816(float* c, const uint32_t* a, const uint32_t* b) {
    asm volatile(
        "mma.sync.aligned.m16n8k16.row.col.f32.f16.f16.f32 "
        "{%0,%1,%2,%3}, {%4,%5,%6,%7}, {%8,%9}, {%0,%1,%2,%3};"
        : "+f"(c[0]), "+f"(c[1]), "+f"(c[2]), "+f"(c[3])
        : "r"(a[0]), "r"(a[1]), "r"(a[2]), "r"(a[3]), "r"(b[0]), "r"(b[1]));
}
__device__ __forceinline__ void cp16(uint32_t dst, const void* src) {
    asm volatile("cp.async.cg.shared.global [%0], [%1], 16;" :: "r"(dst), "l"(src));
}

/* ================ GEMM (R6 skeleton, fp16 2-term: A hi/lo x B single) ================ */
#define APAD   200
#define A_H    0
#define A_L    (128 * APAD * 2)                /* 51200  */
#define B_BASE (2 * 128 * APAD * 2)            /* 102400 */
#define B_STEP 27648                            /* 192 rows x 144 B, single (hi) */
#define GEMM_SMEM (B_BASE + 2 * B_STEP)        /* 157696 */

__global__ __launch_bounds__(256, 1)
void gemm_fp16x2(const float* __restrict__ A,
                 const __half* __restrict__ B,
                 const float* __restrict__ bias,
                 float* __restrict__ C, int ldc, int NT)
{
    extern __shared__ char smc[];
    uint32_t sb;
    asm("{ .reg .u64 t; cvta.to.shared.u64 t, %1; cvt.u32.u64 %0, t; }" : "=r"(sb) : "l"(smc));

    const int tid = threadIdx.x, wid = tid >> 5, lane = tid & 31;
    const int mtile = blockIdx.x;
    const int wm = (wid & 3) * 32;
    const int wn = (wid >> 2) * 96;
    const int L  = 3 * NT;

    auto prefetch = [&](int idx) {
        int nt = idx / 3, kc = idx - nt * 3;
        const __half* bp = B + (size_t)nt * 192 * 192 + kc * 64;
        uint32_t dst = sb + B_BASE + (idx & 1) * B_STEP;
        #pragma unroll
        for (int it = 0; it < 6; it++) {
            int g = tid + it * 256;            /* 1536 groups of 16 B */
            int row = g >> 3, c8 = g & 7;
            cp16(dst + row * 144 + c8 * 16, bp + row * 192 + c8 * 8);
        }
        asm volatile("cp.async.commit_group;" ::: "memory");
    };

    prefetch(0);
    if (L > 1) prefetch(1);

    /* ---- A: load 128x192 fp32, split hi/lo fp16 into smem (once) ---- */
    {
        const float* Abase = A + (size_t)mtile * 128 * 192;
        #pragma unroll
        for (int it = 0; it < 24; it++) {
            int g = tid + it * 256;
            int row = g / 48, c4 = (g % 48) * 4;
            float4 f = *(const float4*)(Abase + row * 192 + c4);
            __half hx = __float2half_rn(f.x), hy = __float2half_rn(f.y);
            __half hz = __float2half_rn(f.z), hw = __float2half_rn(f.w);
            float rx = f.x - __half2float(hx);
            float ry = f.y - __half2float(hy);
            float rz = f.z - __half2float(hz);
            float rw = f.w - __half2float(hw);
            *(uint2*)(smc + A_H + row * 400 + c4 * 2) =
                make_uint2(hpack(hx, hy), hpack(hz, hw));
            *(uint2*)(smc + A_L + row * 400 + c4 * 2) =
                make_uint2(hpack(__float2half_rn(rx), __float2half_rn(ry)),
                           hpack(__float2half_rn(rz), __float2half_rn(rw)));
        }
    }
    __syncthreads();

    float acc[2][12][4];

    for (int nt = 0; nt < NT; nt++) {
        #pragma unroll
        for (int mf = 0; mf < 2; mf++)
            #pragma unroll
            for (int nf = 0; nf < 12; nf++)
                #pragma unroll
                for (int j = 0; j < 4; j++) acc[mf][nf][j] = 0.f;

        for (int kc = 0; kc < 3; kc++) {
            const int idx = nt * 3 + kc;
            if (idx < L - 1) asm volatile("cp.async.wait_group 1;" ::: "memory");
            else             asm volatile("cp.async.wait_group 0;" ::: "memory");
            __syncthreads();

            const char* bb = smc + B_BASE + (idx & 1) * B_STEP;

            #pragma unroll
            for (int ks = 0; ks < 4; ks++) {
                const int kk  = ks * 16 + (lane & 3) * 2;
                const int kxg = kc * 64 + kk;

                uint32_t ah[2][4], al[2][4];
                #pragma unroll
                for (int mf = 0; mf < 2; mf++)
                    #pragma unroll
                    for (int j = 0; j < 4; j++) {
                        int rr = wm + mf * 16 + (lane >> 2) + (j & 1) * 8;
                        int kx = kxg + (j >> 1) * 8;
                        ah[mf][j] = *(const uint32_t*)(smc + A_H + rr * 400 + kx * 2);
                        al[mf][j] = *(const uint32_t*)(smc + A_L + rr * 400 + kx * 2);
                    }

                uint32_t bh[12][2];
                #pragma unroll
                for (int nf = 0; nf < 12; nf++) {
                    int n = wn + nf * 8 + (lane >> 2);
                    bh[nf][0] = *(const uint32_t*)(bb + n * 144 + kk * 2);
                    bh[nf][1] = *(const uint32_t*)(bb + n * 144 + (kk + 8) * 2);
                }

                #pragma unroll
                for (int mf = 0; mf < 2; mf++)
                    #pragma unroll
                    for (int nf = 0; nf < 12; nf++) {
                        mma16816(acc[mf][nf], ah[mf], bh[nf]);
                        mma16816(acc[mf][nf], al[mf], bh[nf]);
                    }
            }
            __syncthreads();
            if (idx + 2 < L) prefetch(idx + 2);
        }

        #pragma unroll
        for (int mf = 0; mf < 2; mf++) {
            size_t r0 = (size_t)mtile * 128 + wm + mf * 16 + (lane >> 2);
            #pragma unroll
            for (int nf = 0; nf < 12; nf++) {
                int c = nt * 192 + wn + nf * 8 + (lane & 3) * 2;
                float b0 = __ldg(bias + c), b1 = __ldg(bias + c + 1);
                *(float2*)(C + r0 * ldc + c) =
                    make_float2(acc[mf][nf][0] + b0, acc[mf][nf][1] + b1);
                *(float2*)(C + (r0 + 8) * ldc + c) =
                    make_float2(acc[mf][nf][2] + b0, acc[mf][nf][3] + b1);
            }
        }
    }
}

/* ================= K2: R5-shape attention, fp16 2-term =================
   128 thr/window, per-head loop. Q hi/lo x K single; P hi/lo x V single. */
__global__ __launch_bounds__(128, 3)
void attn_win()
{
    __shared__ __half sQh[64 * 36], sQl[64 * 36];
    __shared__ __half sKh[56 * 36];
    __shared__ __half sVh[32 * 66];

    const int tid  = threadIdx.x;
    const int wid  = tid >> 5, lane = tid & 31;
    const int b    = blockIdx.x;
    const int l4   = lane >> 2, lm = lane & 3;

    for (int i = tid; i < 64 * 36; i += 128) { sQh[i] = __ushort_as_half(0); sQl[i] = __ushort_as_half(0); }
    for (int i = tid; i < 56 * 36; i += 128) sKh[i] = __ushort_as_half(0);
    for (int i = tid; i < 32 * 66; i += 128) sVh[i] = __ushort_as_half(0);

    const float* qkvw = g_qkv + (size_t)b * (NTOK * 576);
    const int r0 = wid * 16 + l4;

    for (int h = 0; h < HEADS; h++) {
        __syncthreads();
        /* ---- convert: 49x32 q (hi/lo), k, v (single) ---- */
        for (int idx = tid; idx < NTOK * 32; idx += 128) {
            int r = idx >> 5, c = idx & 31;
            const float* rowp = qkvw + r * 576 + h * 32 + c;
            float qv = rowp[0] * QSCALE;
            __half qh = __float2half_rn(qv);
            sQh[r * 36 + c] = qh;
            sQl[r * 36 + c] = __float2half_rn(qv - __half2float(qh));
            sKh[r * 36 + c] = __float2half_rn(rowp[192]);
            sVh[c * 66 + r] = __float2half_rn(rowp[384]);
        }
        __syncthreads();

        /* ---- Q a-frags ---- */
        uint32_t qh[2][4], ql[2][4];
        #pragma unroll
        for (int kf = 0; kf < 2; kf++)
            #pragma unroll
            for (int j = 0; j < 4; j++) {
                int rr = r0 + (j & 1) * 8;
                int kx = kf * 16 + lm * 2 + (j >> 1) * 8;
                qh[kf][j] = *(const uint32_t*)&sQh[rr * 36 + kx];
                ql[kf][j] = *(const uint32_t*)&sQl[rr * 36 + kx];
            }

        /* ---- S = Q K^T (2-term) ---- */
        float acc[7][4];
        #pragma unroll
        for (int nf = 0; nf < 7; nf++)
            #pragma unroll
            for (int j = 0; j < 4; j++) acc[nf][j] = 0.f;

        #pragma unroll
        for (int nf = 0; nf < 7; nf++) {
            int n = nf * 8 + l4;
            #pragma unroll
            for (int kf = 0; kf < 2; kf++) {
                uint32_t bh[2];
                bh[0] = *(const uint32_t*)&sKh[n * 36 + kf * 16 + lm * 2];
                bh[1] = *(const uint32_t*)&sKh[n * 36 + kf * 16 + lm * 2 + 8];
                mma16816(acc[nf], qh[kf], bh);
                mma16816(acc[nf], ql[kf], bh);
            }
        }

        /* ---- softmax ---- */
        const int ra = r0, rb = r0 + 8;
        const float* biasA = g_bias + (h * NTOK + ra) * NTOK;
        const float* biasB = g_bias + (h * NTOK + rb) * NTOK;
        float ma = -1e30f, mb = -1e30f;
        #pragma unroll
        for (int nf = 0; nf < 7; nf++) {
            int c0 = nf * 8 + lm * 2, c1 = c0 + 1;
            float ba0 = (ra < NTOK && c0 < NTOK) ? __ldg(biasA + c0) : 0.f;
            float ba1 = (ra < NTOK && c1 < NTOK) ? __ldg(biasA + c1) : 0.f;
            float bb0 = (rb < NTOK && c0 < NTOK) ? __ldg(biasB + c0) : 0.f;
            float bb1 = (rb < NTOK && c1 < NTOK) ? __ldg(biasB + c1) : 0.f;
            acc[nf][0] = (c0 < NTOK) ? acc[nf][0] + ba0 : -1e30f;
            acc[nf][1] = (c1 < NTOK) ? acc[nf][1] + ba1 : -1e30f;
            acc[nf][2] = (c0 < NTOK) ? acc[nf][2] + bb0 : -1e30f;
            acc[nf][3] = (c1 < NTOK) ? acc[nf][3] + bb1 : -1e30f;
            ma = fmaxf(ma, fmaxf(acc[nf][0], acc[nf][1]));
            mb = fmaxf(mb, fmaxf(acc[nf][2], acc[nf][3]));
        }
        ma = fmaxf(ma, __shfl_xor_sync(0xffffffffu, ma, 1));
        ma = fmaxf(ma, __shfl_xor_sync(0xffffffffu, ma, 2));
        mb = fmaxf(mb, __shfl_xor_sync(0xffffffffu, mb, 1));
        mb = fmaxf(mb, __shfl_xor_sync(0xffffffffu, mb, 2));

        float sa = 0.f, sb2 = 0.f;
        #pragma unroll
        for (int nf = 0; nf < 7; nf++) {
            acc[nf][0] = __expf(acc[nf][0] - ma);
            acc[nf][1] = __expf(acc[nf][1] - ma);
            acc[nf][2] = __expf(acc[nf][2] - mb);
            acc[nf][3] = __expf(acc[nf][3] - mb);
            sa  += acc[nf][0] + acc[nf][1];
            sb2 += acc[nf][2] + acc[nf][3];
        }
        sa  += __shfl_xor_sync(0xffffffffu, sa, 1);
        sa  += __shfl_xor_sync(0xffffffffu, sa, 2);
        sb2 += __shfl_xor_sync(0xffffffffu, sb2, 1);
        sb2 += __shfl_xor_sync(0xffffffffu, sb2, 2);
        float inva = 1.f / sa, invb = 1.f / sb2;
        #pragma unroll
        for (int nf = 0; nf < 7; nf++) {
            acc[nf][0] *= inva; acc[nf][1] *= inva;
            acc[nf][2] *= invb; acc[nf][3] *= invb;
        }

        /* ---- P hi/lo a-frags ---- */
        uint32_t pah[4][4], pal[4][4];
        #pragma unroll
        for (int kf = 0; kf < 4; kf++) {
            #pragma unroll
            for (int half = 0; half < 2; half++) {
                int nf = 2 * kf + half;
                if (nf < 7) {
                    float p0 = acc[nf][0], p1 = acc[nf][1];
                    float p2 = acc[nf][2], p3 = acc[nf][3];
                    __half h0 = __float2half_rn(p0), h1 = __float2half_rn(p1);
                    __half h2 = __float2half_rn(p2), h3 = __float2half_rn(p3);
                    pah[kf][half * 2]     = hpack(h0, h1);
                    pah[kf][half * 2 + 1] = hpack(h2, h3);
                    pal[kf][half * 2]     = hpack(__float2half_rn(p0 - __half2float(h0)),
                                                  __float2half_rn(p1 - __half2float(h1)));
                    pal[kf][half * 2 + 1] = hpack(__float2half_rn(p2 - __half2float(h2)),
                                                  __float2half_rn(p3 - __half2float(h3)));
                } else {
                    pah[kf][half * 2] = 0u; pah[kf][half * 2 + 1] = 0u;
                    pal[kf][half * 2] = 0u; pal[kf][half * 2 + 1] = 0u;
                }
            }
        }

        /* ---- O = P V (2-term) ---- */
        float oacc[4][4];
        #pragma unroll
        for (int nf = 0; nf < 4; nf++)
            #pragma unroll
            for (int j = 0; j < 4; j++) oacc[nf][j] = 0.f;

        #pragma unroll
        for (int nf = 0; nf < 4; nf++) {
            int dh = nf * 8 + l4;
            #pragma unroll
            for (int kf = 0; kf < 4; kf++) {
                uint32_t bh[2];
                bh[0] = *(const uint32_t*)&sVh[dh * 66 + kf * 16 + lm * 2];
                bh[1] = *(const uint32_t*)&sVh[dh * 66 + kf * 16 + lm * 2 + 8];
                mma16816(oacc[nf], pah[kf], bh);
                mma16816(oacc[nf], pal[kf], bh);
            }
        }

        if (ra < NTOK) {
            float* orow = g_attn + ((size_t)b * NTOK + ra) * DIM + h * DH;
            #pragma unroll
            for (int nf = 0; nf < 4; nf++)
                *(float2*)(orow + nf * 8 + lm * 2) = make_float2(oacc[nf][0], oacc[nf][1]);
        }
        if (rb < NTOK) {
            float* orow = g_attn + ((size_t)b * NTOK + rb) * DIM + h * DH;
            #pragma unroll
            for (int nf = 0; nf < 4; nf++)
                *(float2*)(orow + nf * 8 + lm * 2) = make_float2(oacc[nf][2], oacc[nf][3]);
        }
    }
}

/* ================= host ================= */
extern "C" void kernel_launch(void* const* d_in, const int* in_sizes, int n_in,
                              void* d_out, int out_size)
{
    const float* x          = (const float*)d_in[0];
    const float* qkv_w      = (const float*)d_in[1];
    const float* qkv_b      = (const float*)d_in[2];
    const float* proj_w     = (const float*)d_in[3];
    const float* proj_b     = (const float*)d_in[4];
    const float* bias_table = (const float*)d_in[5];
    const int*   rel_idx    = (const int*)d_in[6];
    float*       out        = (float*)d_out;

    const int nB = in_sizes[0] / (NTOK * DIM);       /* 4096 */
    const int mt = (nB * NTOK) / 128;                /* 1568 */

    void *p_qkv, *p_attn, *p_wq, *p_wp;
    cudaGetSymbolAddress(&p_qkv,  g_qkv);
    cudaGetSymbolAddress(&p_attn, g_attn);
    cudaGetSymbolAddress(&p_wq,   g_wq);
    cudaGetSymbolAddress(&p_wp,   g_wp);

    cudaFuncSetAttribute(gemm_fp16x2, cudaFuncAttributeMaxDynamicSharedMemorySize, GEMM_SMEM);

    prep_kernel<<<432, 256>>>(qkv_w, proj_w, bias_table, rel_idx);

    gemm_fp16x2<<<mt, 256, GEMM_SMEM>>>(
        x, (const __half*)p_wq, qkv_b, (float*)p_qkv, 576, 3);

    attn_win<<<nB, 128>>>();

    gemm_fp16x2<<<mt, 256, GEMM_SMEM>>>(
        (const float*)p_attn, (const __half*)p_wp, proj_b, out, 192, 1);
}